// round 11
// baseline (speedup 1.0000x reference)
#include <cuda_runtime.h>
#include <cstdint>

// YOLO loss R11: R8 skeleton (best: cp.async 3-stage ring, 2 blocks/SM,
// 128 threads, static even/odd pair compute) + dead-traffic elimination:
// target channels 5..9 of each odd cell occupy a fully-dead 16B granule
// (pair-floats 36..39) which is never loaded (-3.3% DRAM traffic).
// Deterministic reduction (fixed tile map, fixed-order final sum).

#define NCELLS  (16384 * 7 * 7)    // 802816
#define TILE_C  128                // cells per tile
#define THREADS 128
#define TV4     (TILE_C * 30 / 4)  // 960 float4 per tensor per tile
#define STAGE_V4 (2 * TV4)         // 1920 float4 per stage (pred + tgt w/ holes)
#define NSTAGES 3
#define NTILES  (NCELLS / TILE_C)  // 6272 exact
#define GRID    304                // 152 SMs * 2 blocks
#define SMEM_BYTES (NSTAGES * STAGE_V4 * 16)  // 92160

__device__ float    g_partial[2048];
__device__ unsigned g_count = 0;

__device__ __forceinline__ void cp_async16(void* smem_dst, const void* gmem_src) {
    unsigned saddr = (unsigned)__cvta_generic_to_shared(smem_dst);
    asm volatile("cp.async.cg.shared.global [%0], [%1], 16;\n"
                 :: "r"(saddr), "l"(gmem_src) : "memory");
}
__device__ __forceinline__ void cp_commit() {
    asm volatile("cp.async.commit_group;\n" ::: "memory");
}
template <int N>
__device__ __forceinline__ void cp_wait() {
    asm volatile("cp.async.wait_group %0;\n" :: "n"(N) : "memory");
}

__device__ __forceinline__ float iou_f(float x1, float y1, float w1, float h1,
                                       float x2, float y2, float w2, float h2) {
    float xl = fmaxf(x1 - w1 * 0.5f, x2 - w2 * 0.5f);
    float yt = fmaxf(y1 - h1 * 0.5f, y2 - h2 * 0.5f);
    float xr = fminf(x1 + w1 * 0.5f, x2 + w2 * 0.5f);
    float yb = fminf(y1 + h1 * 0.5f, y2 + h2 * 0.5f);
    bool valid = (xr >= xl) && (yb >= yt);
    float inter = (xr - xl) * (yb - yt);
    float uni = w1 * h1 + w2 * h2 - inter;
    float safe = (uni == 0.0f) ? 1.0f : uni;
    return valid ? (inter / safe) : 0.0f;
}

__device__ __forceinline__ float cell_loss(float t0, float t1, float t2, float t3, float t4,
                                           float p0, float p1, float p2, float p3, float p4,
                                           float p5, float p6, float p7, float p8, float p9,
                                           float cls) {
    float obj   = (t4 > 0.0f)  ? 1.0f : 0.0f;
    float noobj = (t4 == 0.0f) ? 1.0f : 0.0f;

    float dno = t4 - p4;
    float conf_noobj = noobj * dno * dno;

    float iou1 = iou_f(t0, t1, t2, t3, p0, p1, p2, p3);
    float iou2 = iou_f(t0, t1, t2, t3, p5, p6, p7, p8);
    float resp1 = (iou1 > iou2) ? 1.0f : 0.0f;
    float m1 = obj * resp1;
    float m2 = obj * (1.0f - resp1);

    float d1 = iou1 - p4;
    float d2 = iou2 - p9;
    float conf_obj = m1 * d1 * d1 + m2 * d2 * d2;

    float dx1 = t0 - p0, dy1 = t1 - p1;
    float dx2 = t0 - p5, dy2 = t1 - p6;
    float xy = m1 * (dx1 * dx1 + dy1 * dy1) + m2 * (dx2 * dx2 + dy2 * dy2);

    float dw1 = t2 - p2, dh1 = t3 - p3;
    float dw2 = t2 - p7, dh2 = t3 - p8;
    float wh = m1 * (dw1 * dw1 + dh1 * dh1) + m2 * (dw2 * dw2 + dh2 * dh2);

    return 5.0f * (xy + wh) + conf_obj + 0.5f * conf_noobj + obj * cls;
}

// Even cell of a pair (slots 0..7): static mapping.
__device__ __forceinline__ float even_cell(const float4* __restrict__ SP,
                                           const float4* __restrict__ ST) {
    float cls = 0.0f;
#pragma unroll
    for (int j = 3; j <= 6; j++) {
        float4 a = ST[j], b = SP[j];
        float d0 = a.x - b.x, d1 = a.y - b.y, d2 = a.z - b.z, d3 = a.w - b.w;
        cls += d0 * d0 + d1 * d1 + d2 * d2 + d3 * d3;
    }
    float4 P2 = SP[2], T2 = ST[2];
    { float d0 = T2.z - P2.z, d1 = T2.w - P2.w; cls += d0 * d0 + d1 * d1; }
    float4 P7 = SP[7], T7 = ST[7];
    { float d0 = T7.x - P7.x, d1 = T7.y - P7.y; cls += d0 * d0 + d1 * d1; }

    float4 P0 = SP[0], P1 = SP[1], T0 = ST[0], T1 = ST[1];
    return cell_loss(T0.x, T0.y, T0.z, T0.w, T1.x,
                     P0.x, P0.y, P0.z, P0.w, P1.x,
                     P1.y, P1.z, P1.w, P2.x, P2.y, cls);
}

// Odd cell of a pair (slots 7..14, never slot 9 of tgt): static mapping.
__device__ __forceinline__ float odd_cell(const float4* __restrict__ SP,
                                          const float4* __restrict__ ST) {
    float cls = 0.0f;
#pragma unroll
    for (int j = 10; j <= 14; j++) {
        float4 a = ST[j], b = SP[j];
        float d0 = a.x - b.x, d1 = a.y - b.y, d2 = a.z - b.z, d3 = a.w - b.w;
        cls += d0 * d0 + d1 * d1 + d2 * d2 + d3 * d3;
    }
    float4 P7 = SP[7], P8 = SP[8], P9 = SP[9];
    float4 T7 = ST[7], T8 = ST[8];
    return cell_loss(T7.z, T7.w, T8.x, T8.y, T8.z,
                     P7.z, P7.w, P8.x, P8.y, P8.z,
                     P8.w, P9.x, P9.y, P9.z, P9.w, cls);
}

// Stage one tile: pred = all 960 granules; tgt = 896 live granules
// (skip granule 9 of each 15-granule pair: odd-cell tgt channels 6..9, dead).
__device__ __forceinline__ void prefetch_tile(float4* sbuf, int s,
                                              const float4* __restrict__ gp,
                                              const float4* __restrict__ gt,
                                              int tile, int tid) {
    float4* dst = sbuf + s * STAGE_V4;
    const float4* srcp = gp + (size_t)tile * TV4;
    const float4* srct = gt + (size_t)tile * TV4;
    float4* dstt = dst + TV4;

    // pred: 960 = 7*128 + 64
#pragma unroll
    for (int k = 0; k < 7; k++) {
        int i = k * THREADS + tid;
        cp_async16(dst + i, srcp + i);
    }
    if (tid < 64) {
        int i = 896 + tid;
        cp_async16(dst + i, srcp + i);
    }

    // tgt: 896 live granules = 7*128; live j -> pair j/14, slot j%14 (+1 if >=9)
#pragma unroll
    for (int k = 0; k < 7; k++) {
        int j = k * THREADS + tid;          // 0..895
        int pr = j / 14;
        int g  = j - pr * 14;
        g += (g >= 9) ? 1 : 0;
        int off = pr * 15 + g;              // 0..959, never slot 9
        cp_async16(dstt + off, srct + off);
    }
}

__global__ void __launch_bounds__(THREADS)
yolo_fused_kernel(const float* __restrict__ pred,
                  const float* __restrict__ tgt,
                  float* __restrict__ out) {
    extern __shared__ float4 sbuf[];       // 3 stages x 1920 float4
    __shared__ float swarp[THREADS / 32];
    __shared__ int   s_isLast;

    const int tid  = threadIdx.x;
    const int lane = tid & 31;
    const int wid  = tid >> 5;
    const float4* gp = reinterpret_cast<const float4*>(pred);
    const float4* gt = reinterpret_cast<const float4*>(tgt);

    float loss = 0.0f;

    int t = blockIdx.x;
    int stage = 0;

    if (t < NTILES)        prefetch_tile(sbuf, 0, gp, gt, t, tid);
    cp_commit();
    if (t + GRID < NTILES) prefetch_tile(sbuf, 1, gp, gt, t + GRID, tid);
    cp_commit();

    while (t < NTILES) {
        int t2 = t + 2 * GRID;
        if (t2 < NTILES) {
            prefetch_tile(sbuf, (stage + 2) % NSTAGES, gp, gt, t2, tid);
            cp_commit();
            cp_wait<2>();            // current tile's group has landed
        } else if (t + GRID < NTILES) {
            cp_commit();             // empty group keeps the count aligned
            cp_wait<2>();
        } else {
            cp_wait<0>();
        }
        __syncthreads();

        {
            // warp w: (w&1 ? odd : even) cell of pair (w>>1)*32 + lane.
            int pair = ((wid >> 1) << 5) + lane;
            const float4* SP = sbuf + stage * STAGE_V4 + pair * 15;
            const float4* ST = SP + TV4;
            loss += (wid & 1) ? odd_cell(SP, ST) : even_cell(SP, ST);
        }
        __syncthreads();             // all reads done before this stage is refilled
        stage = (stage + 1) % NSTAGES;
        t += GRID;
    }

    // ---- block reduce (deterministic) ----
#pragma unroll
    for (int off = 16; off > 0; off >>= 1)
        loss += __shfl_down_sync(0xFFFFFFFFu, loss, off);

    if (lane == 0) swarp[wid] = loss;
    __syncthreads();

    if (tid == 0) {
        g_partial[blockIdx.x] = swarp[0] + swarp[1] + swarp[2] + swarp[3];
        __threadfence();
        unsigned v = atomicAdd(&g_count, 1u);
        s_isLast = (v == (unsigned)(gridDim.x - 1)) ? 1 : 0;
    }
    __syncthreads();

    // ---- last block: deterministic final reduction ----
    if (s_isLast) {
        __shared__ double sd[THREADS];
        double acc = 0.0;
        for (int i = tid; i < GRID; i += THREADS)
            acc += (double)g_partial[i];
        sd[tid] = acc;
        __syncthreads();
#pragma unroll
        for (int stride = THREADS / 2; stride > 0; stride >>= 1) {
            if (tid < stride) sd[tid] += sd[tid + stride];
            __syncthreads();
        }
        if (tid == 0) {
            out[0] = (float)(sd[0] / 16384.0);
            g_count = 0;   // reset for next graph replay
        }
    }
}

extern "C" void kernel_launch(void* const* d_in, const int* in_sizes, int n_in,
                              void* d_out, int out_size) {
    const float* y  = (const float*)d_in[0];
    const float* gt = (const float*)d_in[1];
    float* out = (float*)d_out;

    static int attr_done = 0;
    if (!attr_done) {
        cudaFuncSetAttribute(yolo_fused_kernel,
                             cudaFuncAttributeMaxDynamicSharedMemorySize, SMEM_BYTES);
        attr_done = 1;
    }

    yolo_fused_kernel<<<GRID, THREADS, SMEM_BYTES>>>(y, gt, out);
}

// round 12
// speedup vs baseline: 1.0130x; 1.0130x over previous
#include <cuda_runtime.h>
#include <cstdint>

// YOLO loss R12: hybrid of the two best measured designs.
// R5 shape: 2-stage cp.async ring, 30KB tiles, 3 blocks/SM (GRID=456).
// R8 compute: all 4 warps active (warp w -> (w&1?odd:even) cell of pair
// (w>>1)*32+lane), halving the per-tile compute bubble.
// Deterministic reduction (fixed tile map, fixed-order final sum).

#define NCELLS  (16384 * 7 * 7)    // 802816
#define TILE_C  128                // cells per tile
#define THREADS 128
#define TV4     (TILE_C * 30 / 4)  // 960 float4 per tensor per tile
#define STAGE_V4 (2 * TV4)         // 1920 float4 per stage (pred + tgt)
#define NSTAGES 2
#define NTILES  (NCELLS / TILE_C)  // 6272 exact
#define GRID    456                // 152 SMs * 3 blocks
#define SMEM_BYTES (NSTAGES * STAGE_V4 * 16)  // 61440

__device__ float    g_partial[2048];
__device__ unsigned g_count = 0;

__device__ __forceinline__ void cp_async16(void* smem_dst, const void* gmem_src) {
    unsigned saddr = (unsigned)__cvta_generic_to_shared(smem_dst);
    asm volatile("cp.async.cg.shared.global [%0], [%1], 16;\n"
                 :: "r"(saddr), "l"(gmem_src) : "memory");
}
__device__ __forceinline__ void cp_commit() {
    asm volatile("cp.async.commit_group;\n" ::: "memory");
}
template <int N>
__device__ __forceinline__ void cp_wait() {
    asm volatile("cp.async.wait_group %0;\n" :: "n"(N) : "memory");
}

__device__ __forceinline__ float iou_f(float x1, float y1, float w1, float h1,
                                       float x2, float y2, float w2, float h2) {
    float xl = fmaxf(x1 - w1 * 0.5f, x2 - w2 * 0.5f);
    float yt = fmaxf(y1 - h1 * 0.5f, y2 - h2 * 0.5f);
    float xr = fminf(x1 + w1 * 0.5f, x2 + w2 * 0.5f);
    float yb = fminf(y1 + h1 * 0.5f, y2 + h2 * 0.5f);
    bool valid = (xr >= xl) && (yb >= yt);
    float inter = (xr - xl) * (yb - yt);
    float uni = w1 * h1 + w2 * h2 - inter;
    float safe = (uni == 0.0f) ? 1.0f : uni;
    return valid ? (inter / safe) : 0.0f;
}

__device__ __forceinline__ float cell_loss(float t0, float t1, float t2, float t3, float t4,
                                           float p0, float p1, float p2, float p3, float p4,
                                           float p5, float p6, float p7, float p8, float p9,
                                           float cls) {
    float obj   = (t4 > 0.0f)  ? 1.0f : 0.0f;
    float noobj = (t4 == 0.0f) ? 1.0f : 0.0f;

    float dno = t4 - p4;
    float conf_noobj = noobj * dno * dno;

    float iou1 = iou_f(t0, t1, t2, t3, p0, p1, p2, p3);
    float iou2 = iou_f(t0, t1, t2, t3, p5, p6, p7, p8);
    float resp1 = (iou1 > iou2) ? 1.0f : 0.0f;
    float m1 = obj * resp1;
    float m2 = obj * (1.0f - resp1);

    float d1 = iou1 - p4;
    float d2 = iou2 - p9;
    float conf_obj = m1 * d1 * d1 + m2 * d2 * d2;

    float dx1 = t0 - p0, dy1 = t1 - p1;
    float dx2 = t0 - p5, dy2 = t1 - p6;
    float xy = m1 * (dx1 * dx1 + dy1 * dy1) + m2 * (dx2 * dx2 + dy2 * dy2);

    float dw1 = t2 - p2, dh1 = t3 - p3;
    float dw2 = t2 - p7, dh2 = t3 - p8;
    float wh = m1 * (dw1 * dw1 + dh1 * dh1) + m2 * (dw2 * dw2 + dh2 * dh2);

    return 5.0f * (xy + wh) + conf_obj + 0.5f * conf_noobj + obj * cls;
}

// Even cell of a pair (slots 0..7): static mapping.
__device__ __forceinline__ float even_cell(const float4* __restrict__ SP,
                                           const float4* __restrict__ ST) {
    float cls = 0.0f;
#pragma unroll
    for (int j = 3; j <= 6; j++) {
        float4 a = ST[j], b = SP[j];
        float d0 = a.x - b.x, d1 = a.y - b.y, d2 = a.z - b.z, d3 = a.w - b.w;
        cls += d0 * d0 + d1 * d1 + d2 * d2 + d3 * d3;
    }
    float4 P2 = SP[2], T2 = ST[2];
    { float d0 = T2.z - P2.z, d1 = T2.w - P2.w; cls += d0 * d0 + d1 * d1; }
    float4 P7 = SP[7], T7 = ST[7];
    { float d0 = T7.x - P7.x, d1 = T7.y - P7.y; cls += d0 * d0 + d1 * d1; }

    float4 P0 = SP[0], P1 = SP[1], T0 = ST[0], T1 = ST[1];
    return cell_loss(T0.x, T0.y, T0.z, T0.w, T1.x,
                     P0.x, P0.y, P0.z, P0.w, P1.x,
                     P1.y, P1.z, P1.w, P2.x, P2.y, cls);
}

// Odd cell of a pair (slots 7..14): static mapping.
__device__ __forceinline__ float odd_cell(const float4* __restrict__ SP,
                                          const float4* __restrict__ ST) {
    float cls = 0.0f;
#pragma unroll
    for (int j = 10; j <= 14; j++) {
        float4 a = ST[j], b = SP[j];
        float d0 = a.x - b.x, d1 = a.y - b.y, d2 = a.z - b.z, d3 = a.w - b.w;
        cls += d0 * d0 + d1 * d1 + d2 * d2 + d3 * d3;
    }
    float4 P7 = SP[7], P8 = SP[8], P9 = SP[9];
    float4 T7 = ST[7], T8 = ST[8];
    return cell_loss(T7.z, T7.w, T8.x, T8.y, T8.z,
                     P7.z, P7.w, P8.x, P8.y, P8.z,
                     P8.w, P9.x, P9.y, P9.z, P9.w, cls);
}

__device__ __forceinline__ void prefetch_tile(float4* sbuf, int s,
                                              const float4* __restrict__ gp,
                                              const float4* __restrict__ gt,
                                              int tile, int tid) {
    float4* dst = sbuf + s * STAGE_V4;
    const float4* srcp = gp + (size_t)tile * TV4;
    const float4* srct = gt + (size_t)tile * TV4;
#pragma unroll
    for (int k = 0; k < 15; k++) {
        int i = k * THREADS + tid;               // 0..1919
        const float4* src = (i < TV4) ? (srcp + i) : (srct + (i - TV4));
        cp_async16(dst + i, src);
    }
}

__global__ void __launch_bounds__(THREADS)
yolo_fused_kernel(const float* __restrict__ pred,
                  const float* __restrict__ tgt,
                  float* __restrict__ out) {
    extern __shared__ float4 sbuf[];       // 2 stages x 1920 float4
    __shared__ float swarp[THREADS / 32];
    __shared__ int   s_isLast;

    const int tid  = threadIdx.x;
    const int lane = tid & 31;
    const int wid  = tid >> 5;
    const float4* gp = reinterpret_cast<const float4*>(pred);
    const float4* gt = reinterpret_cast<const float4*>(tgt);

    float loss = 0.0f;

    int t = blockIdx.x;
    int stage = 0;
    if (t < NTILES) prefetch_tile(sbuf, 0, gp, gt, t, tid);
    cp_commit();

    while (t < NTILES) {
        int tn = t + GRID;
        if (tn < NTILES) {
            prefetch_tile(sbuf, stage ^ 1, gp, gt, tn, tid);
            cp_commit();
            cp_wait<1>();            // current tile's group has landed
        } else {
            cp_wait<0>();
        }
        __syncthreads();

        {
            // warp w: (w&1 ? odd : even) cell of pair (w>>1)*32 + lane.
            int pair = ((wid >> 1) << 5) + lane;
            const float4* SP = sbuf + stage * STAGE_V4 + pair * 15;
            const float4* ST = SP + TV4;
            loss += (wid & 1) ? odd_cell(SP, ST) : even_cell(SP, ST);
        }
        __syncthreads();             // all reads done before this stage refills
        stage ^= 1;
        t = tn;
    }

    // ---- block reduce (deterministic) ----
#pragma unroll
    for (int off = 16; off > 0; off >>= 1)
        loss += __shfl_down_sync(0xFFFFFFFFu, loss, off);

    if (lane == 0) swarp[wid] = loss;
    __syncthreads();

    if (tid == 0) {
        g_partial[blockIdx.x] = swarp[0] + swarp[1] + swarp[2] + swarp[3];
        __threadfence();
        unsigned v = atomicAdd(&g_count, 1u);
        s_isLast = (v == (unsigned)(gridDim.x - 1)) ? 1 : 0;
    }
    __syncthreads();

    // ---- last block: deterministic final reduction ----
    if (s_isLast) {
        __shared__ double sd[THREADS];
        double acc = 0.0;
        for (int i = tid; i < GRID; i += THREADS)
            acc += (double)g_partial[i];
        sd[tid] = acc;
        __syncthreads();
#pragma unroll
        for (int stride = THREADS / 2; stride > 0; stride >>= 1) {
            if (tid < stride) sd[tid] += sd[tid + stride];
            __syncthreads();
        }
        if (tid == 0) {
            out[0] = (float)(sd[0] / 16384.0);
            g_count = 0;   // reset for next graph replay
        }
    }
}

extern "C" void kernel_launch(void* const* d_in, const int* in_sizes, int n_in,
                              void* d_out, int out_size) {
    const float* y  = (const float*)d_in[0];
    const float* gt = (const float*)d_in[1];
    float* out = (float*)d_out;

    static int attr_done = 0;
    if (!attr_done) {
        cudaFuncSetAttribute(yolo_fused_kernel,
                             cudaFuncAttributeMaxDynamicSharedMemorySize, SMEM_BYTES);
        attr_done = 1;
    }

    yolo_fused_kernel<<<GRID, THREADS, SMEM_BYTES>>>(y, gt, out);
}